// round 7
// baseline (speedup 1.0000x reference)
#include <cuda_runtime.h>
#include <cstdint>

#define Bn 2
#define Nn 6
#define Dn 59
#define FHn 16
#define FWn 44
#define Cn 80
#define Xn 256
#define Yn 256

// scratch layout: [b][y][x][c], c contiguous
__device__ float g_scratch[(size_t)Bn * Yn * Xn * Cn];

// XLA strength-reduced dot: each product individually rounded, then summed
// left-to-right (j ascending). NO fma anywhere.
__device__ __forceinline__ float dot3m(float m0, float m1, float m2,
                                       float v0, float v1, float v2) {
    float p0 = __fmul_rn(m0, v0);
    float p1 = __fmul_rn(m1, v1);
    float p2 = __fmul_rn(m2, v2);
    return __fadd_rn(__fadd_rn(p0, p1), p2);
}

// adjugate inverse in fp32 — exact on identity (dataset post_rots / l2e_rots)
__device__ __forceinline__ void inv3_adj(const float* m, float* o) {
    float a = m[0], b = m[1], c = m[2];
    float d = m[3], e = m[4], f = m[5];
    float g = m[6], h = m[7], i = m[8];
    float A  = __fadd_rn(__fmul_rn(e, i), -__fmul_rn(f, h));
    float Bc = -__fadd_rn(__fmul_rn(d, i), -__fmul_rn(f, g));
    float Cc = __fadd_rn(__fmul_rn(d, h), -__fmul_rn(e, g));
    float det = __fadd_rn(__fadd_rn(__fmul_rn(a, A), __fmul_rn(b, Bc)), __fmul_rn(c, Cc));
    float r = __fdiv_rn(1.0f, det);
    o[0] = __fmul_rn(A, r);
    o[1] = __fmul_rn(__fadd_rn(__fmul_rn(c, h), -__fmul_rn(b, i)), r);
    o[2] = __fmul_rn(__fadd_rn(__fmul_rn(b, f), -__fmul_rn(c, e)), r);
    o[3] = __fmul_rn(Bc, r);
    o[4] = __fmul_rn(__fadd_rn(__fmul_rn(a, i), -__fmul_rn(c, g)), r);
    o[5] = __fmul_rn(__fadd_rn(__fmul_rn(c, d), -__fmul_rn(a, f)), r);
    o[6] = __fmul_rn(Cc, r);
    o[7] = __fmul_rn(__fadd_rn(__fmul_rn(b, g), -__fmul_rn(a, h)), r);
    o[8] = __fmul_rn(__fadd_rn(__fmul_rn(a, e), -__fmul_rn(b, d)), r);
}

// LAPACK strti2-style upper-triangular fp32 inverse (dataset intrins is
// upper triangular with pivot-free LU).
__device__ __forceinline__ void inv3_lapack_tri(const float* m, float* o) {
    float A01 = m[1], A02 = m[2], A12 = m[5];
    float i00 = __fdiv_rn(1.0f, m[0]);
    float i11 = __fdiv_rn(1.0f, m[4]);
    float i22 = __fdiv_rn(1.0f, m[8]);
    float x0c1 = __fmul_rn(A01, i00);
    float i01 = -__fmul_rn(i11, x0c1);
    float x0 = __fmul_rn(A02, i00);
    x0 = __fadd_rn(x0, __fmul_rn(A12, i01));   // i01==0 on dataset
    float x1 = __fmul_rn(A12, i11);
    float i02 = -__fmul_rn(i22, x0);
    float i12 = -__fmul_rn(i22, x1);
    o[0] = i00; o[1] = i01; o[2] = i02;
    o[3] = 0.f; o[4] = i11; o[5] = i12;
    o[6] = 0.f; o[7] = 0.f; o[8] = i22;
}

__global__ void zero_scratch_kernel() {
    const size_t n4 = (size_t)Bn * Yn * Xn * Cn / 4;
    float4* p = reinterpret_cast<float4*>(g_scratch);
    float4 z = make_float4(0.f, 0.f, 0.f, 0.f);
    for (size_t i = (size_t)blockIdx.x * blockDim.x + threadIdx.x; i < n4;
         i += (size_t)gridDim.x * blockDim.x)
        p[i] = z;
}

// one block per (b,n,h,w) column; 256 threads
__global__ void pool_kernel(const float* __restrict__ x,
                            const float* __restrict__ rots,
                            const float* __restrict__ trans,
                            const float* __restrict__ intrins,
                            const float* __restrict__ post_rots,
                            const float* __restrict__ post_trans,
                            const float* __restrict__ l2e_rots,
                            const float* __restrict__ l2e_trans) {
    int col = blockIdx.x;
    int w = col % FWn; int t1 = col / FWn;
    int h = t1 % FHn;  t1 /= FHn;
    int n = t1 % Nn;   int b = t1 / Nn;

    __shared__ float sA[9];    // inv(post_rots)
    __shared__ float sC[9];    // combine = rots @ inv(intrins)
    __shared__ float sIL[9];   // inv(l2e_rots)
    __shared__ float sTr[3];   // trans
    __shared__ float sLT[3];   // l2e_trans
    __shared__ float sPT[3];   // post_trans
    __shared__ int   svox[Dn];

    if (threadIdx.x == 0) {
        int bn = b * Nn + n;
        float invI[9];
        inv3_adj(post_rots + bn * 9, sA);
        inv3_lapack_tri(intrins + bn * 9, invI);
        inv3_adj(l2e_rots + b * 9, sIL);
        const float* R = rots + bn * 9;
        // combine matmul: strength-reduced mul+add, j ascending
        #pragma unroll
        for (int r = 0; r < 3; r++)
            #pragma unroll
            for (int c = 0; c < 3; c++)
                sC[r * 3 + c] = dot3m(R[r * 3 + 0], R[r * 3 + 1], R[r * 3 + 2],
                                      invI[0 * 3 + c], invI[1 * 3 + c], invI[2 * 3 + c]);
        #pragma unroll
        for (int k = 0; k < 3; k++) {
            sTr[k] = trans[bn * 3 + k];
            sLT[k] = l2e_trans[b * 3 + k];
            sPT[k] = post_trans[bn * 3 + k];
        }
    }
    __syncthreads();

    if (threadIdx.x < Dn) {
        int d = threadIdx.x;
        // frustum: u = fl(w * fl(703/43)), v = fl(h * fl(255/15)), dep = d+1
        float ustep = __fdiv_rn(703.0f, 43.0f);
        float vstep = __fdiv_rn(255.0f, 15.0f);
        float u = __fmul_rn((float)w, ustep);
        float v = __fmul_rn((float)h, vstep);
        float dep = (float)(d + 1);
        // pts = frustum - post_trans
        float f0 = __fadd_rn(u, -sPT[0]);
        float f1 = __fadd_rn(v, -sPT[1]);
        float f2 = __fadd_rn(dep, -sPT[2]);
        // einsum 1: inv(post_rots) @ pts  (mul+add, j ascending)
        float p1x = dot3m(sA[0], sA[1], sA[2], f0, f1, f2);
        float p1y = dot3m(sA[3], sA[4], sA[5], f0, f1, f2);
        float p1z = dot3m(sA[6], sA[7], sA[8], f0, f1, f2);
        // unproject: (xy * z, z)
        float p2x = __fmul_rn(p1x, p1z);
        float p2y = __fmul_rn(p1y, p1z);
        float p2z = p1z;
        // einsum 2: combine @ pts, then + trans (separate rounded add)
        float e0 = __fadd_rn(dot3m(sC[0], sC[1], sC[2], p2x, p2y, p2z), sTr[0]);
        float e1 = __fadd_rn(dot3m(sC[3], sC[4], sC[5], p2x, p2y, p2z), sTr[1]);
        float e2 = __fadd_rn(dot3m(sC[6], sC[7], sC[8], p2x, p2y, p2z), sTr[2]);
        // - l2e_trans
        e0 = __fadd_rn(e0, -sLT[0]);
        e1 = __fadd_rn(e1, -sLT[1]);
        e2 = __fadd_rn(e2, -sLT[2]);
        // einsum 3: inv(l2e_rots) @ pts
        float gx = dot3m(sIL[0], sIL[1], sIL[2], e0, e1, e2);
        float gy = dot3m(sIL[3], sIL[4], sIL[5], e0, e1, e2);
        float gz = dot3m(sIL[6], sIL[7], sIL[8], e0, e1, e2);
        // coords = trunc((g - fl(BX - fl(DX*0.5))) * fl(1/DX))
        // XLA algebraic simplifier: div-by-const -> mul-by-recip.
        // fl32(1/0.4f) == 2.5f exactly; fl32(1/8.0f) == 0.125f exactly.
        float oxy = __fadd_rn(-51.0f, -__fmul_rn(0.4f, 0.5f));  // fl(-51.2)
        float ozz = __fadd_rn(-1.0f, -__fmul_rn(8.0f, 0.5f));   // -5 exact
        int c0 = (int)__fmul_rn(__fadd_rn(gx, -oxy), 2.5f);
        int c1 = (int)__fmul_rn(__fadd_rn(gy, -oxy), 2.5f);
        int c2 = (int)__fmul_rn(__fadd_rn(gz, -ozz), 0.125f);
        bool kept = (c0 >= 0) && (c0 < Xn) && (c1 >= 0) && (c1 < Yn) && (c2 == 0);
        svox[d] = kept ? ((((b * Yn) + c1) * Xn + c0) * Cn) : -1;
    }
    __syncthreads();

    // x layout: [B][N][D][FH][FW][C]
    const size_t colbase = ((size_t)(b * Nn + n) * Dn * FHn * FWn
                            + (size_t)(h * FWn + w)) * Cn;
    const size_t dstride = (size_t)FHn * FWn * Cn;

    for (int i = threadIdx.x; i < Dn * Cn; i += blockDim.x) {
        int d = i / Cn;
        int c = i - d * Cn;
        int vox = svox[d];
        if (vox >= 0) {
            float val = x[colbase + (size_t)d * dstride + c];
            atomicAdd(&g_scratch[(size_t)vox + c], val);
        }
    }
}

// transpose scratch [b][y][x][c] -> out [b][c][y][x]; one block per (b, y, x-half)
__global__ void transpose_kernel(float* __restrict__ out) {
    int blk = blockIdx.x;                  // 0 .. B*Y*2-1
    int xhalf = blk & 1;
    int y = (blk >> 1) & (Yn - 1);
    int b = blk >> 9;

    __shared__ float tile[128 * 81];

    const float* src = g_scratch
        + (((size_t)(b * Yn + y) * Xn) + (size_t)xhalf * 128) * Cn;

    #pragma unroll 4
    for (int i = threadIdx.x; i < 128 * Cn; i += 256) {
        int xl = i / Cn;
        int c  = i - xl * Cn;
        tile[xl * 81 + c] = src[i];
    }
    __syncthreads();

    #pragma unroll 4
    for (int i = threadIdx.x; i < 128 * Cn; i += 256) {
        int c  = i >> 7;       // i / 128
        int xl = i & 127;      // i % 128
        size_t dst = (((size_t)(b * Cn + c) * Yn + y) << 8) + (size_t)xhalf * 128 + xl;
        out[dst] = tile[xl * 81 + c];
    }
}

extern "C" void kernel_launch(void* const* d_in, const int* in_sizes, int n_in,
                              void* d_out, int out_size) {
    const float* x          = (const float*)d_in[0];
    const float* rots       = (const float*)d_in[1];
    const float* trans      = (const float*)d_in[2];
    const float* intrins    = (const float*)d_in[3];
    const float* post_rots  = (const float*)d_in[4];
    const float* post_trans = (const float*)d_in[5];
    const float* l2e_rots   = (const float*)d_in[6];
    const float* l2e_trans  = (const float*)d_in[7];
    float* out = (float*)d_out;

    zero_scratch_kernel<<<2048, 256>>>();

    int ncols = Bn * Nn * FHn * FWn;   // 8448
    pool_kernel<<<ncols, 256>>>(x, rots, trans, intrins, post_rots, post_trans,
                                l2e_rots, l2e_trans);

    transpose_kernel<<<Bn * Yn * 2, 256>>>(out);
}